// round 3
// baseline (speedup 1.0000x reference)
#include <cuda_runtime.h>
#include <math.h>
#include <stdint.h>

#define SEQ    4096
#define HID    768
#define NHEAD  12
#define HD     64
#define NBATCH 2
#define NOUT   2304   // 3*HID

// Scratch: y = x @ W^T + b, natural [B, S, 2304] layout.
// Per (b,h): Q = y_flat[b*S*NOUT + h*3*S*HD], contiguous [S, HD]; K, V follow.
__device__ float g_y[NBATCH * SEQ * NOUT];

__device__ __forceinline__ float fast_exp2(float x) {
    float y;
    asm("ex2.approx.f32 %0, %1;" : "=f"(y) : "f"(x));
    return y;
}

// ---------------------------------------------------------------------------
// QKV GEMM: y[m][n] = sum_k X[m][k] * W[n][k] + bias[n]
// M = B*S = 8192, N = 2304, K = 768.  BM=BN=128, BK=8, 256 thr, 8x8/thread.
// ---------------------------------------------------------------------------
__global__ __launch_bounds__(256) void qkv_gemm(const float* __restrict__ X,
                                                const float* __restrict__ W,
                                                const float* __restrict__ bias) {
    __shared__ float Ast[8][128];   // [k][m]
    __shared__ float Bst[8][128];   // [k][n]

    const int tid = threadIdx.x;
    const int tx  = tid & 15;       // n direction
    const int ty  = tid >> 4;       // m direction
    const int mBase = blockIdx.y * 128;
    const int nBase = blockIdx.x * 128;

    const int lr = tid >> 1;            // 0..127 (tile row)
    const int lk = (tid & 1) * 4;       // 0 or 4 (k sub-offset)

    const float* Ap = X + (size_t)(mBase + lr) * HID + lk;
    const float* Bp = W + (size_t)(nBase + lr) * HID + lk;

    float4 ar = *(const float4*)Ap;
    float4 br = *(const float4*)Bp;

    float acc[8][8];
#pragma unroll
    for (int i = 0; i < 8; i++)
#pragma unroll
        for (int j = 0; j < 8; j++) acc[i][j] = 0.0f;

    for (int kt = 0; kt < 96; kt++) {
        Ast[lk + 0][lr] = ar.x; Ast[lk + 1][lr] = ar.y;
        Ast[lk + 2][lr] = ar.z; Ast[lk + 3][lr] = ar.w;
        Bst[lk + 0][lr] = br.x; Bst[lk + 1][lr] = br.y;
        Bst[lk + 2][lr] = br.z; Bst[lk + 3][lr] = br.w;
        __syncthreads();

        if (kt < 95) {
            ar = *(const float4*)(Ap + (kt + 1) * 8);
            br = *(const float4*)(Bp + (kt + 1) * 8);
        }

#pragma unroll
        for (int k = 0; k < 8; k++) {
            float a[8], b[8];
            *(float4*)(a + 0) = *(float4*)&Ast[k][ty * 8 + 0];
            *(float4*)(a + 4) = *(float4*)&Ast[k][ty * 8 + 4];
            *(float4*)(b + 0) = *(float4*)&Bst[k][tx * 8 + 0];
            *(float4*)(b + 4) = *(float4*)&Bst[k][tx * 8 + 4];
#pragma unroll
            for (int i = 0; i < 8; i++)
#pragma unroll
                for (int j = 0; j < 8; j++)
                    acc[i][j] = fmaf(a[i], b[j], acc[i][j]);
        }
        __syncthreads();
    }

#pragma unroll
    for (int i = 0; i < 8; i++) {
        const size_t row = (size_t)(mBase + ty * 8 + i);
#pragma unroll
        for (int j4 = 0; j4 < 8; j4 += 4) {
            const int n = nBase + tx * 8 + j4;
            float4 o;
            o.x = acc[i][j4 + 0] + __ldg(&bias[n + 0]);
            o.y = acc[i][j4 + 1] + __ldg(&bias[n + 1]);
            o.z = acc[i][j4 + 2] + __ldg(&bias[n + 2]);
            o.w = acc[i][j4 + 3] + __ldg(&bias[n + 3]);
            *(float4*)(g_y + row * NOUT + n) = o;
        }
    }
}

// ---------------------------------------------------------------------------
// Flash attention: per block = one (b,h) and one 64-row q tile.
// Thread (tx,ty): S rows ty*4+i, S cols tx+16*j  (strided cols -> LDS of K
// fragments is bank-conflict-free: group = (tx+16j)*17 + d4 = tx+d4 mod 8).
// smem: Qs[64][64], Ps[64][64], Ks[64][68], Vs[64][68].  3 syncs/iter.
// ---------------------------------------------------------------------------
#define KVSTRIDE 68
#define ATTN_SMEM ((4096 + 4096 + 2 * 64 * KVSTRIDE) * 4)   // 67584 bytes

__global__ __launch_bounds__(256, 2) void attn_kernel(float* __restrict__ out) {
    extern __shared__ float sm[];
    float* Qs = sm;                     // [64][64]  reads ty-broadcast
    float* Ps = sm + 4096;              // [64][64]  reads ty-broadcast
    float* Ks = sm + 8192;              // [64][68]
    float* Vs = Ks + 64 * KVSTRIDE;     // [64][68]

    const int tid = threadIdx.x;
    const int tx = tid & 15;   // col-group direction
    const int ty = tid >> 4;   // q direction
    const int qt = blockIdx.x;                 // 0..63
    const int b  = blockIdx.y / NHEAD;
    const int h  = blockIdx.y % NHEAD;

    const float* Qp = g_y + (size_t)b * SEQ * NOUT + (size_t)h * (3 * SEQ * HD);
    const float* Kp = Qp + SEQ * HD;
    const float* Vp = Kp + SEQ * HD;

    const float SC = 0.125f * 1.4426950408889634f;   // 1/sqrt(64) * log2(e)

    // load Q tile (prescaled by SC): 1024 float4, 4 per thread
#pragma unroll
    for (int i = 0; i < 4; i++) {
        const int idx = tid + i * 256;
        const int r = idx >> 4;
        const int c = (idx & 15) << 2;
        float4 v = *(const float4*)(Qp + (size_t)(qt * 64 + r) * HD + c);
        v.x *= SC; v.y *= SC; v.z *= SC; v.w *= SC;
        *(float4*)(Qs + r * 64 + c) = v;
    }

    float acc[4][4];
    float m[4], l[4];
#pragma unroll
    for (int i = 0; i < 4; i++) {
        m[i] = -INFINITY; l[i] = 0.0f;
#pragma unroll
        for (int j = 0; j < 4; j++) acc[i][j] = 0.0f;
    }

    for (int kc = 0; kc < 64; kc++) {
        const float* Kc = Kp + (size_t)kc * 64 * HD;
        const float* Vc = Vp + (size_t)kc * 64 * HD;

        __syncthreads();   // previous iter's PV reads of Vs/Ps complete
        // load K and V chunks [64][64] -> stride-68 buffers
#pragma unroll
        for (int i = 0; i < 4; i++) {
            const int idx = tid + i * 256;
            const int r = idx >> 4;
            const int c = (idx & 15) << 2;
            *(float4*)(Ks + r * KVSTRIDE + c) = *(const float4*)(Kc + r * HD + c);
            *(float4*)(Vs + r * KVSTRIDE + c) = *(const float4*)(Vc + r * HD + c);
        }
        __syncthreads();   // K,V ready

        // S = Q * K^T ; thread col j -> key row (tx + 16*j)
        float s[4][4];
#pragma unroll
        for (int i = 0; i < 4; i++)
#pragma unroll
            for (int j = 0; j < 4; j++) s[i][j] = 0.0f;

#pragma unroll
        for (int d4 = 0; d4 < 16; d4++) {
            float4 q[4], k[4];
#pragma unroll
            for (int i = 0; i < 4; i++)
                q[i] = *(float4*)(Qs + (ty * 4 + i) * 64 + d4 * 4);
#pragma unroll
            for (int j = 0; j < 4; j++)
                k[j] = *(float4*)(Ks + (tx + 16 * j) * KVSTRIDE + d4 * 4);
#pragma unroll
            for (int i = 0; i < 4; i++)
#pragma unroll
                for (int j = 0; j < 4; j++) {
                    s[i][j] = fmaf(q[i].x, k[j].x, s[i][j]);
                    s[i][j] = fmaf(q[i].y, k[j].y, s[i][j]);
                    s[i][j] = fmaf(q[i].z, k[j].z, s[i][j]);
                    s[i][j] = fmaf(q[i].w, k[j].w, s[i][j]);
                }
        }

        // online softmax (base-2), per q-row; reduce across 16 tx lanes
#pragma unroll
        for (int i = 0; i < 4; i++) {
            float rm = fmaxf(fmaxf(s[i][0], s[i][1]), fmaxf(s[i][2], s[i][3]));
#pragma unroll
            for (int off = 8; off >= 1; off >>= 1)
                rm = fmaxf(rm, __shfl_xor_sync(0xffffffffu, rm, off));
            const float mnew = fmaxf(m[i], rm);
            const float corr = fast_exp2(m[i] - mnew);
            float rs = 0.0f;
#pragma unroll
            for (int j = 0; j < 4; j++) {
                s[i][j] = fast_exp2(s[i][j] - mnew);
                rs += s[i][j];
            }
#pragma unroll
            for (int off = 8; off >= 1; off >>= 1)
                rs += __shfl_xor_sync(0xffffffffu, rs, off);
            l[i] = l[i] * corr + rs;
            m[i] = mnew;
#pragma unroll
            for (int j = 0; j < 4; j++) acc[i][j] *= corr;
        }

        // write P tile (scalar, col = tx + 16*j; 2-way write conflict max)
#pragma unroll
        for (int i = 0; i < 4; i++)
#pragma unroll
            for (int j = 0; j < 4; j++)
                Ps[(ty * 4 + i) * 64 + tx + 16 * j] = s[i][j];
        __syncthreads();   // Ps ready

        // O += P * V  (p reads ty-broadcast; v reads conflict-free)
#pragma unroll
        for (int k4 = 0; k4 < 16; k4++) {
            float4 p[4], v[4];
#pragma unroll
            for (int i = 0; i < 4; i++)
                p[i] = *(float4*)(Ps + (ty * 4 + i) * 64 + k4 * 4);
#pragma unroll
            for (int kk = 0; kk < 4; kk++)
                v[kk] = *(float4*)(Vs + (k4 * 4 + kk) * KVSTRIDE + tx * 4);
#pragma unroll
            for (int i = 0; i < 4; i++) {
                acc[i][0] = fmaf(p[i].x, v[0].x, acc[i][0]);
                acc[i][1] = fmaf(p[i].x, v[0].y, acc[i][1]);
                acc[i][2] = fmaf(p[i].x, v[0].z, acc[i][2]);
                acc[i][3] = fmaf(p[i].x, v[0].w, acc[i][3]);
                acc[i][0] = fmaf(p[i].y, v[1].x, acc[i][0]);
                acc[i][1] = fmaf(p[i].y, v[1].y, acc[i][1]);
                acc[i][2] = fmaf(p[i].y, v[1].z, acc[i][2]);
                acc[i][3] = fmaf(p[i].y, v[1].w, acc[i][3]);
                acc[i][0] = fmaf(p[i].z, v[2].x, acc[i][0]);
                acc[i][1] = fmaf(p[i].z, v[2].y, acc[i][1]);
                acc[i][2] = fmaf(p[i].z, v[2].z, acc[i][2]);
                acc[i][3] = fmaf(p[i].z, v[2].w, acc[i][3]);
                acc[i][0] = fmaf(p[i].w, v[3].x, acc[i][0]);
                acc[i][1] = fmaf(p[i].w, v[3].y, acc[i][1]);
                acc[i][2] = fmaf(p[i].w, v[3].z, acc[i][2]);
                acc[i][3] = fmaf(p[i].w, v[3].w, acc[i][3]);
            }
        }
    }

    // epilogue: divide by l, write out[b][q][h*64 + d]  (d = tx*4 .. tx*4+3)
#pragma unroll
    for (int i = 0; i < 4; i++) {
        const float inv = 1.0f / l[i];
        const int q = qt * 64 + ty * 4 + i;
        float4 o;
        o.x = acc[i][0] * inv; o.y = acc[i][1] * inv;
        o.z = acc[i][2] * inv; o.w = acc[i][3] * inv;
        *(float4*)(out + (size_t)b * SEQ * HID + (size_t)q * HID + h * HD + tx * 4) = o;
    }
}

// ---------------------------------------------------------------------------
extern "C" void kernel_launch(void* const* d_in, const int* in_sizes, int n_in,
                              void* d_out, int out_size) {
    const float* x    = (const float*)d_in[0];
    const float* W    = (const float*)d_in[1];
    const float* bias = (const float*)d_in[2];
    float* out = (float*)d_out;

    cudaFuncSetAttribute(attn_kernel,
                         cudaFuncAttributeMaxDynamicSharedMemorySize, ATTN_SMEM);

    qkv_gemm<<<dim3(NOUT / 128, (NBATCH * SEQ) / 128), 256>>>(x, W, bias);
    attn_kernel<<<dim3(SEQ / 64, NBATCH * NHEAD), 256, ATTN_SMEM>>>(out);
}

// round 6
// speedup vs baseline: 1.6466x; 1.6466x over previous
#include <cuda_runtime.h>
#include <cuda_bf16.h>
#include <math.h>
#include <stdint.h>

#define SEQ    4096
#define HID    768
#define NHEAD  12
#define HD     64
#define NBATCH 2
#define NOUT   2304   // 3*HID

// Scratch y. Q,K blocks: natural flat layout (contiguous [4096 x 64] per (b,h)).
// V blocks: stored TRANSPOSED [64 d][4096 s] by the GEMM epilogue.
__device__ float g_y[NBATCH * SEQ * NOUT];

__device__ __forceinline__ float fast_exp2(float x) {
    float y;
    asm("ex2.approx.f32 %0, %1;" : "=f"(y) : "f"(x));
    return y;
}

// split float pair into packed bf16x2 hi and lo (first elem = low 16 bits)
__device__ __forceinline__ void split_pack(float a, float b,
                                           uint32_t& hi, uint32_t& lo) {
    __nv_bfloat16 ah = __float2bfloat16(a);
    __nv_bfloat16 bh = __float2bfloat16(b);
    __nv_bfloat16 al = __float2bfloat16(a - __bfloat162float(ah));
    __nv_bfloat16 bl = __float2bfloat16(b - __bfloat162float(bh));
    hi = (uint32_t)__bfloat16_as_ushort(ah) | ((uint32_t)__bfloat16_as_ushort(bh) << 16);
    lo = (uint32_t)__bfloat16_as_ushort(al) | ((uint32_t)__bfloat16_as_ushort(bl) << 16);
}

// m16n8k16 bf16 MMA, D/C fp32 in-place accumulate
__device__ __forceinline__ void mma16816(float* d, const uint32_t* a,
                                         uint32_t b0, uint32_t b1) {
    asm volatile(
        "mma.sync.aligned.m16n8k16.row.col.f32.bf16.bf16.f32 "
        "{%0,%1,%2,%3}, {%4,%5,%6,%7}, {%8,%9}, {%0,%1,%2,%3};"
        : "+f"(d[0]), "+f"(d[1]), "+f"(d[2]), "+f"(d[3])
        : "r"(a[0]), "r"(a[1]), "r"(a[2]), "r"(a[3]), "r"(b0), "r"(b1));
}

// ---------------------------------------------------------------------------
// QKV GEMM (fp32 SIMT) with V blocks written TRANSPOSED [d][s].
// ---------------------------------------------------------------------------
__global__ __launch_bounds__(256) void qkv_gemm(const float* __restrict__ X,
                                                const float* __restrict__ W,
                                                const float* __restrict__ bias) {
    __shared__ float Ast[8][128];
    __shared__ float Bst[8][128];

    const int tid = threadIdx.x;
    const int tx  = tid & 15;
    const int ty  = tid >> 4;
    const int mBase = blockIdx.y * 128;
    const int nBase = blockIdx.x * 128;
    const int lr = tid >> 1;
    const int lk = (tid & 1) * 4;

    const float* Ap = X + (size_t)(mBase + lr) * HID + lk;
    const float* Bp = W + (size_t)(nBase + lr) * HID + lk;

    float4 ar = *(const float4*)Ap;
    float4 br = *(const float4*)Bp;

    float acc[8][8];
#pragma unroll
    for (int i = 0; i < 8; i++)
#pragma unroll
        for (int j = 0; j < 8; j++) acc[i][j] = 0.0f;

    for (int kt = 0; kt < 96; kt++) {
        Ast[lk + 0][lr] = ar.x; Ast[lk + 1][lr] = ar.y;
        Ast[lk + 2][lr] = ar.z; Ast[lk + 3][lr] = ar.w;
        Bst[lk + 0][lr] = br.x; Bst[lk + 1][lr] = br.y;
        Bst[lk + 2][lr] = br.z; Bst[lk + 3][lr] = br.w;
        __syncthreads();
        if (kt < 95) {
            ar = *(const float4*)(Ap + (kt + 1) * 8);
            br = *(const float4*)(Bp + (kt + 1) * 8);
        }
#pragma unroll
        for (int k = 0; k < 8; k++) {
            float a[8], b[8];
            *(float4*)(a + 0) = *(float4*)&Ast[k][ty * 8 + 0];
            *(float4*)(a + 4) = *(float4*)&Ast[k][ty * 8 + 4];
            *(float4*)(b + 0) = *(float4*)&Bst[k][tx * 8 + 0];
            *(float4*)(b + 4) = *(float4*)&Bst[k][tx * 8 + 4];
#pragma unroll
            for (int i = 0; i < 8; i++)
#pragma unroll
                for (int j = 0; j < 8; j++)
                    acc[i][j] = fmaf(a[i], b[j], acc[i][j]);
        }
        __syncthreads();
    }

#pragma unroll
    for (int i = 0; i < 8; i++) {
        const int row = mBase + ty * 8 + i;          // 0..8191
        const int s   = row & 4095;
        const size_t bb = (size_t)(row >> 12) * (SEQ * (size_t)NOUT);
#pragma unroll
        for (int j4 = 0; j4 < 8; j4 += 4) {
            const int n = nBase + tx * 8 + j4;
            float4 o;
            o.x = acc[i][j4 + 0] + __ldg(&bias[n + 0]);
            o.y = acc[i][j4 + 1] + __ldg(&bias[n + 1]);
            o.z = acc[i][j4 + 2] + __ldg(&bias[n + 2]);
            o.w = acc[i][j4 + 3] + __ldg(&bias[n + 3]);
            const uint32_t fb = (uint32_t)s * NOUT + n;     // flat-in-batch idx
            const uint32_t g  = fb >> 18;                   // 0..35 = h*3 + t
            if ((g % 3u) != 2u) {
                *(float4*)(g_y + bb + fb) = o;              // Q/K: natural
            } else {
                const uint32_t o18 = fb & 0x3FFFFu;
                const uint32_t d0  = o18 & 63u;
                const uint32_t s2  = o18 >> 6;
                float* vb = g_y + bb + (size_t)g * 262144 + s2;
                vb[(size_t)(d0 + 0) * SEQ] = o.x;
                vb[(size_t)(d0 + 1) * SEQ] = o.y;
                vb[(size_t)(d0 + 2) * SEQ] = o.z;
                vb[(size_t)(d0 + 3) * SEQ] = o.w;
            }
        }
    }
}

// ---------------------------------------------------------------------------
// FA2-style flash attention with mma.sync m16n8k16 bf16 (split hi/lo).
// CTA: 128 threads (4 warps), 64 q rows (warp w -> rows w*16..+15),
// key chunks of 64. K smem [key][d], V smem [d][key], row stride 72 bf16.
// ---------------------------------------------------------------------------
#define KSTR_B 144                          // 72 bf16 * 2 bytes
#define SM_KH  0
#define SM_KL  9216
#define SM_VH  18432
#define SM_VL  27648

__global__ __launch_bounds__(128) void attn_mma(float* __restrict__ out) {
    __shared__ __align__(16) unsigned char sm[36864];

    const int tid  = threadIdx.x;
    const int w    = tid >> 5;
    const int lane = tid & 31;
    const int g    = lane >> 2;     // groupID (row within fragment)
    const int tig  = lane & 3;      // thread-in-group

    const int qt = blockIdx.x;                 // 0..63
    const int b  = blockIdx.y / NHEAD;
    const int h  = blockIdx.y % NHEAD;

    const float* base = g_y + (size_t)b * (SEQ * (size_t)NOUT)
                            + (size_t)h * (3 * SEQ * HD);
    const float* Qp = base;
    const float* Kp = base + SEQ * HD;
    const float* Vt = base + 2 * SEQ * HD;     // [64 d][4096 s]

    const float SC = 0.125f * 1.4426950408889634f;   // 1/sqrt(64)*log2(e)
    const int rowbase = qt * 64 + w * 16;

    // ---- Q fragments (registers, whole kernel): a0..a3 per 16-wide k tile ----
    uint32_t qh[4][4], ql[4][4];
#pragma unroll
    for (int kt = 0; kt < 4; kt++)
#pragma unroll
        for (int rr = 0; rr < 2; rr++)
#pragma unroll
            for (int cc = 0; cc < 2; cc++) {
                const float2 v = *(const float2*)(Qp
                    + (size_t)(rowbase + g + rr * 8) * HD + kt * 16 + tig * 2 + cc * 8);
                uint32_t hi, lo;
                split_pack(v.x * SC, v.y * SC, hi, lo);
                qh[kt][rr + cc * 2] = hi;
                ql[kt][rr + cc * 2] = lo;
            }

    float o[8][4];
#pragma unroll
    for (int n = 0; n < 8; n++)
#pragma unroll
        for (int j = 0; j < 4; j++) o[n][j] = 0.0f;
    float m0 = -INFINITY, m1 = -INFINITY, l0 = 0.0f, l1 = 0.0f;

    for (int kc = 0; kc < 64; kc++) {
        __syncthreads();   // previous chunk's fragment reads done
        // ---- K chunk [64 k][64 d] -> KH/KL ----
        const float* Kc = Kp + (size_t)kc * (64 * HD);
#pragma unroll
        for (int i = 0; i < 8; i++) {
            const int idx = tid + i * 128;
            const int r = idx >> 4, c = (idx & 15) * 4;
            const float4 v = *(const float4*)(Kc + (size_t)r * HD + c);
            uint32_t h0, lo0, h1, lo1;
            split_pack(v.x, v.y, h0, lo0);
            split_pack(v.z, v.w, h1, lo1);
            const uint32_t off = (uint32_t)(r * KSTR_B + c * 2);
            *(uint32_t*)(sm + SM_KH + off)     = h0;
            *(uint32_t*)(sm + SM_KH + off + 4) = h1;
            *(uint32_t*)(sm + SM_KL + off)     = lo0;
            *(uint32_t*)(sm + SM_KL + off + 4) = lo1;
        }
        // ---- V chunk [64 d][64 k] -> VH/VL (gmem already [d][s]) ----
#pragma unroll
        for (int i = 0; i < 8; i++) {
            const int idx = tid + i * 128;
            const int d = idx >> 4, k = (idx & 15) * 4;
            const float4 v = *(const float4*)(Vt + (size_t)d * SEQ + (size_t)kc * 64 + k);
            uint32_t h0, lo0, h1, lo1;
            split_pack(v.x, v.y, h0, lo0);
            split_pack(v.z, v.w, h1, lo1);
            const uint32_t off = (uint32_t)(d * KSTR_B + k * 2);
            *(uint32_t*)(sm + SM_VH + off)     = h0;
            *(uint32_t*)(sm + SM_VH + off + 4) = h1;
            *(uint32_t*)(sm + SM_VL + off)     = lo0;
            *(uint32_t*)(sm + SM_VL + off + 4) = lo1;
        }
        __syncthreads();

        // ---- S = Q K^T : 8 n-tiles (keys) x 4 k-tiles (d) x 3 combos ----
        float s[8][4];
#pragma unroll
        for (int n = 0; n < 8; n++) {
            s[n][0] = s[n][1] = s[n][2] = s[n][3] = 0.0f;
            const uint32_t rb = (uint32_t)((n * 8 + g) * KSTR_B);
#pragma unroll
            for (int t = 0; t < 4; t++) {
                const uint32_t co = rb + (uint32_t)((t * 16 + tig * 2) * 2);
                const uint32_t bh0 = *(const uint32_t*)(sm + SM_KH + co);
                const uint32_t bh1 = *(const uint32_t*)(sm + SM_KH + co + 16);
                const uint32_t bl0 = *(const uint32_t*)(sm + SM_KL + co);
                const uint32_t bl1 = *(const uint32_t*)(sm + SM_KL + co + 16);
                mma16816(s[n], qh[t], bh0, bh1);
                mma16816(s[n], ql[t], bh0, bh1);
                mma16816(s[n], qh[t], bl0, bl1);
            }
        }

        // ---- online softmax: rows r0=g, r1=g+8; reduce over quad lanes ----
        float rm0 = -INFINITY, rm1 = -INFINITY;
#pragma unroll
        for (int n = 0; n < 8; n++) {
            rm0 = fmaxf(rm0, fmaxf(s[n][0], s[n][1]));
            rm1 = fmaxf(rm1, fmaxf(s[n][2], s[n][3]));
        }
        rm0 = fmaxf(rm0, __shfl_xor_sync(0xffffffffu, rm0, 1));
        rm0 = fmaxf(rm0, __shfl_xor_sync(0xffffffffu, rm0, 2));
        rm1 = fmaxf(rm1, __shfl_xor_sync(0xffffffffu, rm1, 1));
        rm1 = fmaxf(rm1, __shfl_xor_sync(0xffffffffu, rm1, 2));

        const float mn0 = fmaxf(m0, rm0), mn1 = fmaxf(m1, rm1);
        const float c0 = fast_exp2(m0 - mn0), c1 = fast_exp2(m1 - mn1);
        m0 = mn0; m1 = mn1;
#pragma unroll
        for (int n = 0; n < 8; n++) {
            o[n][0] *= c0; o[n][1] *= c0;
            o[n][2] *= c1; o[n][3] *= c1;
        }
        float ps0 = 0.0f, ps1 = 0.0f;
#pragma unroll
        for (int n = 0; n < 8; n++) {
            s[n][0] = fast_exp2(s[n][0] - mn0);
            s[n][1] = fast_exp2(s[n][1] - mn0);
            s[n][2] = fast_exp2(s[n][2] - mn1);
            s[n][3] = fast_exp2(s[n][3] - mn1);
            ps0 += s[n][0] + s[n][1];
            ps1 += s[n][2] + s[n][3];
        }
        ps0 += __shfl_xor_sync(0xffffffffu, ps0, 1);
        ps0 += __shfl_xor_sync(0xffffffffu, ps0, 2);
        ps1 += __shfl_xor_sync(0xffffffffu, ps1, 1);
        ps1 += __shfl_xor_sync(0xffffffffu, ps1, 2);
        l0 = l0 * c0 + ps0;
        l1 = l1 * c1 + ps1;

        // ---- P -> A fragments (D layout == A layout; split hi/lo) ----
        uint32_t ph[4][4], pl[4][4];
#pragma unroll
        for (int t = 0; t < 4; t++) {
            split_pack(s[2 * t][0],     s[2 * t][1],     ph[t][0], pl[t][0]);
            split_pack(s[2 * t][2],     s[2 * t][3],     ph[t][1], pl[t][1]);
            split_pack(s[2 * t + 1][0], s[2 * t + 1][1], ph[t][2], pl[t][2]);
            split_pack(s[2 * t + 1][2], s[2 * t + 1][3], ph[t][3], pl[t][3]);
        }

        // ---- O += P V : 8 n-tiles (d) x 4 k-tiles (keys) x 3 combos ----
#pragma unroll
        for (int n = 0; n < 8; n++) {
            const uint32_t rb = (uint32_t)((n * 8 + g) * KSTR_B);
#pragma unroll
            for (int t = 0; t < 4; t++) {
                const uint32_t co = rb + (uint32_t)((t * 16 + tig * 2) * 2);
                const uint32_t vh0 = *(const uint32_t*)(sm + SM_VH + co);
                const uint32_t vh1 = *(const uint32_t*)(sm + SM_VH + co + 16);
                const uint32_t vl0 = *(const uint32_t*)(sm + SM_VL + co);
                const uint32_t vl1 = *(const uint32_t*)(sm + SM_VL + co + 16);
                mma16816(o[n], ph[t], vh0, vh1);
                mma16816(o[n], pl[t], vh0, vh1);
                mma16816(o[n], ph[t], vl0, vl1);
            }
        }
    }

    // ---- epilogue ----
    const float inv0 = 1.0f / l0, inv1 = 1.0f / l1;
    const int q0 = qt * 64 + w * 16 + g;
    float* ob = out + (size_t)b * SEQ * HID + (size_t)h * HD;
#pragma unroll
    for (int n = 0; n < 8; n++) {
        float2 w0, w1;
        w0.x = o[n][0] * inv0; w0.y = o[n][1] * inv0;
        w1.x = o[n][2] * inv1; w1.y = o[n][3] * inv1;
        *(float2*)(ob + (size_t)q0 * HID + n * 8 + tig * 2)       = w0;
        *(float2*)(ob + (size_t)(q0 + 8) * HID + n * 8 + tig * 2) = w1;
    }
}

// ---------------------------------------------------------------------------
extern "C" void kernel_launch(void* const* d_in, const int* in_sizes, int n_in,
                              void* d_out, int out_size) {
    const float* x    = (const float*)d_in[0];
    const float* W    = (const float*)d_in[1];
    const float* bias = (const float*)d_in[2];
    float* out = (float*)d_out;

    qkv_gemm<<<dim3(NOUT / 128, (NBATCH * SEQ) / 128), 256>>>(x, W, bias);
    attn_mma<<<dim3(SEQ / 64, NBATCH * NHEAD), 128>>>(out);
}

// round 8
// speedup vs baseline: 1.8130x; 1.1011x over previous
#include <cuda_runtime.h>
#include <cuda_bf16.h>
#include <math.h>
#include <stdint.h>

#define SEQ    4096
#define HID    768
#define NHEAD  12
#define HD     64
#define NBATCH 2
#define NOUT   2304   // 3*HID

// Split-bf16 scratch: hi and lo halves of y = x@W^T + b.
// Q blocks pre-scaled by 1/8*log2(e). Q,K natural [s][d]; V transposed [d][s].
__device__ __nv_bfloat16 g_yh[NBATCH * SEQ * NOUT];
__device__ __nv_bfloat16 g_yl[NBATCH * SEQ * NOUT];

__device__ __forceinline__ float fast_exp2(float x) {
    float y;
    asm("ex2.approx.f32 %0, %1;" : "=f"(y) : "f"(x));
    return y;
}

// split float pair into packed bf16x2 hi and lo (first elem = low 16 bits)
__device__ __forceinline__ void split_pack(float a, float b,
                                           uint32_t& hi, uint32_t& lo) {
    __nv_bfloat16 ah = __float2bfloat16(a);
    __nv_bfloat16 bh = __float2bfloat16(b);
    __nv_bfloat16 al = __float2bfloat16(a - __bfloat162float(ah));
    __nv_bfloat16 bl = __float2bfloat16(b - __bfloat162float(bh));
    hi = (uint32_t)__bfloat16_as_ushort(ah) | ((uint32_t)__bfloat16_as_ushort(bh) << 16);
    lo = (uint32_t)__bfloat16_as_ushort(al) | ((uint32_t)__bfloat16_as_ushort(bl) << 16);
}
__device__ __forceinline__ void split1(float a, __nv_bfloat16& h, __nv_bfloat16& l) {
    h = __float2bfloat16(a);
    l = __float2bfloat16(a - __bfloat162float(h));
}

// m16n8k16 bf16 MMA, D/C fp32 in-place accumulate
__device__ __forceinline__ void mma16816(float* d, const uint32_t* a,
                                         uint32_t b0, uint32_t b1) {
    asm volatile(
        "mma.sync.aligned.m16n8k16.row.col.f32.bf16.bf16.f32 "
        "{%0,%1,%2,%3}, {%4,%5,%6,%7}, {%8,%9}, {%0,%1,%2,%3};"
        : "+f"(d[0]), "+f"(d[1]), "+f"(d[2]), "+f"(d[3])
        : "r"(a[0]), "r"(a[1]), "r"(a[2]), "r"(a[3]), "r"(b0), "r"(b1));
}

__device__ __forceinline__ uint32_t smem_u32(const void* p) {
    uint32_t a;
    asm("{ .reg .u64 t; cvta.to.shared.u64 t, %1; cvt.u32.u64 %0, t; }"
        : "=r"(a) : "l"(p));
    return a;
}
#define CP16(dst, src) \
    asm volatile("cp.async.cg.shared.global [%0], [%1], 16;" \
                 :: "r"(dst), "l"(src) : "memory")
#define CP_COMMIT() asm volatile("cp.async.commit_group;" ::: "memory")
#define CP_WAIT1()  asm volatile("cp.async.wait_group 1;" ::: "memory")
#define CP_WAIT0()  asm volatile("cp.async.wait_group 0;" ::: "memory")

// ---------------------------------------------------------------------------
// QKV GEMM (fp32 SIMT) with split-bf16 epilogue.
// ---------------------------------------------------------------------------
__global__ __launch_bounds__(256) void qkv_gemm(const float* __restrict__ X,
                                                const float* __restrict__ W,
                                                const float* __restrict__ bias) {
    __shared__ float Ast[8][128];
    __shared__ float Bst[8][128];

    const int tid = threadIdx.x;
    const int tx  = tid & 15;
    const int ty  = tid >> 4;
    const int mBase = blockIdx.y * 128;
    const int nBase = blockIdx.x * 128;
    const int lr = tid >> 1;
    const int lk = (tid & 1) * 4;

    const float* Ap = X + (size_t)(mBase + lr) * HID + lk;
    const float* Bp = W + (size_t)(nBase + lr) * HID + lk;

    float4 ar = *(const float4*)Ap;
    float4 br = *(const float4*)Bp;

    float acc[8][8];
#pragma unroll
    for (int i = 0; i < 8; i++)
#pragma unroll
        for (int j = 0; j < 8; j++) acc[i][j] = 0.0f;

    for (int kt = 0; kt < 96; kt++) {
        Ast[lk + 0][lr] = ar.x; Ast[lk + 1][lr] = ar.y;
        Ast[lk + 2][lr] = ar.z; Ast[lk + 3][lr] = ar.w;
        Bst[lk + 0][lr] = br.x; Bst[lk + 1][lr] = br.y;
        Bst[lk + 2][lr] = br.z; Bst[lk + 3][lr] = br.w;
        __syncthreads();
        if (kt < 95) {
            ar = *(const float4*)(Ap + (kt + 1) * 8);
            br = *(const float4*)(Bp + (kt + 1) * 8);
        }
#pragma unroll
        for (int k = 0; k < 8; k++) {
            float a[8], b[8];
            *(float4*)(a + 0) = *(float4*)&Ast[k][ty * 8 + 0];
            *(float4*)(a + 4) = *(float4*)&Ast[k][ty * 8 + 4];
            *(float4*)(b + 0) = *(float4*)&Bst[k][tx * 8 + 0];
            *(float4*)(b + 4) = *(float4*)&Bst[k][tx * 8 + 4];
#pragma unroll
            for (int i = 0; i < 8; i++)
#pragma unroll
                for (int j = 0; j < 8; j++)
                    acc[i][j] = fmaf(a[i], b[j], acc[i][j]);
        }
        __syncthreads();
    }

    const float SC = 0.125f * 1.4426950408889634f;   // applied to Q blocks only

#pragma unroll
    for (int i = 0; i < 8; i++) {
        const int row = mBase + ty * 8 + i;          // 0..8191
        const int s   = row & 4095;
        const size_t bb = (size_t)(row >> 12) * (SEQ * (size_t)NOUT);
#pragma unroll
        for (int j4 = 0; j4 < 8; j4 += 4) {
            const int n = nBase + tx * 8 + j4;
            float4 o;
            o.x = acc[i][j4 + 0] + __ldg(&bias[n + 0]);
            o.y = acc[i][j4 + 1] + __ldg(&bias[n + 1]);
            o.z = acc[i][j4 + 2] + __ldg(&bias[n + 2]);
            o.w = acc[i][j4 + 3] + __ldg(&bias[n + 3]);
            const uint32_t fb = (uint32_t)s * NOUT + n;     // flat-in-batch idx
            const uint32_t g  = fb >> 18;                   // 0..35 = h*3 + t
            const uint32_t t3 = g % 3u;
            if (t3 != 2u) {
                if (t3 == 0u) { o.x *= SC; o.y *= SC; o.z *= SC; o.w *= SC; }
                uint32_t h0, l0, h1, l1;
                split_pack(o.x, o.y, h0, l0);
                split_pack(o.z, o.w, h1, l1);
                uint2 hv; hv.x = h0; hv.y = h1;
                uint2 lv; lv.x = l0; lv.y = l1;
                *(uint2*)(g_yh + bb + fb) = hv;
                *(uint2*)(g_yl + bb + fb) = lv;
            } else {
                const uint32_t o18 = fb & 0x3FFFFu;
                const uint32_t d0  = o18 & 63u;
                const uint32_t s2  = o18 >> 6;
                __nv_bfloat16* vh = g_yh + bb + (size_t)g * 262144 + s2;
                __nv_bfloat16* vl = g_yl + bb + (size_t)g * 262144 + s2;
                __nv_bfloat16 hh, ll;
                split1(o.x, hh, ll); vh[(size_t)(d0+0)*SEQ] = hh; vl[(size_t)(d0+0)*SEQ] = ll;
                split1(o.y, hh, ll); vh[(size_t)(d0+1)*SEQ] = hh; vl[(size_t)(d0+1)*SEQ] = ll;
                split1(o.z, hh, ll); vh[(size_t)(d0+2)*SEQ] = hh; vl[(size_t)(d0+2)*SEQ] = ll;
                split1(o.w, hh, ll); vh[(size_t)(d0+3)*SEQ] = hh; vl[(size_t)(d0+3)*SEQ] = ll;
            }
        }
    }
}

// ---------------------------------------------------------------------------
// FA2-style flash attention, mma.sync bf16 split hi/lo, cp.async double-buffer.
// CTA: 128 threads (4 warps), 64 q rows; key chunks of 64.
// smem per buffer: KH,KL [64 k][64 d] + VH,VL [64 d][64 k], row stride 144 B.
// ---------------------------------------------------------------------------
#define KSTR_B 144                          // 72 bf16 * 2 bytes
#define SM_KH  0
#define SM_KL  9216
#define SM_VH  18432
#define SM_VL  27648
#define BUFSZ  36864
#define ATTN_SMEM (2 * BUFSZ)               // 73728 bytes

__global__ __launch_bounds__(128) void attn_mma(float* __restrict__ out) {
    extern __shared__ __align__(16) unsigned char smraw[];
    const uint32_t sb = smem_u32(smraw);

    const int tid  = threadIdx.x;
    const int w    = tid >> 5;
    const int lane = tid & 31;
    const int g    = lane >> 2;     // groupID (row within fragment)
    const int tig  = lane & 3;      // thread-in-group

    const int qt = blockIdx.x;                 // 0..63
    const int b  = blockIdx.y / NHEAD;
    const int h  = blockIdx.y % NHEAD;

    const size_t boff = (size_t)b * (SEQ * (size_t)NOUT) + (size_t)h * (3 * SEQ * HD);
    const __nv_bfloat16* Qh16 = g_yh + boff;
    const __nv_bfloat16* Ql16 = g_yl + boff;
    const char* Kh8 = (const char*)(g_yh + boff + SEQ * HD);
    const char* Kl8 = (const char*)(g_yl + boff + SEQ * HD);
    const char* Vh8 = (const char*)(g_yh + boff + 2 * SEQ * HD);  // [d][s]
    const char* Vl8 = (const char*)(g_yl + boff + 2 * SEQ * HD);

    const int rowbase = qt * 64 + w * 16;

    // per-thread cp.async slice: 4 segs per array; seg = tid + i*128
    // K chunk kc: row r (0..63) at gmem kc*8192 + r*128 + c ; smem r*144 + c
    // V chunk kc: row d (0..63) at gmem d*(SEQ*2) + kc*128 + c
    int cr[4], cc[4];
#pragma unroll
    for (int i = 0; i < 4; i++) {
        const int seg = tid + i * 128;
        cr[i] = seg >> 3;
        cc[i] = (seg & 7) * 16;
    }

#define COPY_CHUNK(kcc, bufbase) do {                                          \
    const size_t kofsK = (size_t)(kcc) * 8192;  /* 64 keys * 128 B/row */      \
    const size_t kofsV = (size_t)(kcc) * 128;   /* 64 keys * 2 B */            \
    const uint32_t _sb = (bufbase);                                            \
_Pragma("unroll")                                                              \
    for (int i = 0; i < 4; i++) {                                              \
        const uint32_t so = (uint32_t)(cr[i] * KSTR_B + cc[i]);                \
        const size_t   gk = kofsK + (size_t)cr[i] * 128 + cc[i];               \
        const size_t   gv = (size_t)cr[i] * (SEQ * 2) + kofsV + cc[i];         \
        CP16(_sb + SM_KH + so, Kh8 + gk);                                      \
        CP16(_sb + SM_KL + so, Kl8 + gk);                                      \
        CP16(_sb + SM_VH + so, Vh8 + gv);                                      \
        CP16(_sb + SM_VL + so, Vl8 + gv);                                      \
    }                                                                          \
} while (0)

    // ---- Q fragments (hi/lo already split + scaled in gmem) ----
    uint32_t qh[4][4], ql[4][4];
#pragma unroll
    for (int kt = 0; kt < 4; kt++)
#pragma unroll
        for (int rr = 0; rr < 2; rr++)
#pragma unroll
            for (int cc2 = 0; cc2 < 2; cc2++) {
                const size_t eo = (size_t)(rowbase + g + rr * 8) * HD
                                + kt * 16 + tig * 2 + cc2 * 8;
                qh[kt][rr + cc2 * 2] = *(const uint32_t*)(Qh16 + eo);
                ql[kt][rr + cc2 * 2] = *(const uint32_t*)(Ql16 + eo);
            }

    float o[8][4];
#pragma unroll
    for (int n = 0; n < 8; n++)
#pragma unroll
        for (int j = 0; j < 4; j++) o[n][j] = 0.0f;
    float m0 = -INFINITY, m1 = -INFINITY, l0 = 0.0f, l1 = 0.0f;

    COPY_CHUNK(0, sb);
    CP_COMMIT();

    for (int kc = 0; kc < 64; kc++) {
        if (kc < 63) {
            COPY_CHUNK(kc + 1, sb + (uint32_t)((kc + 1) & 1) * BUFSZ);
            CP_COMMIT();
            CP_WAIT1();
        } else {
            CP_WAIT0();
        }
        __syncthreads();                 // chunk kc visible to all threads

        const unsigned char* bufp = smraw + (kc & 1) * BUFSZ;

        // ---- S = Q K^T : 8 n-tiles (keys) x 4 k-tiles (d) x 3 combos ----
        float s[8][4];
#pragma unroll
        for (int n = 0; n < 8; n++) {
            s[n][0] = s[n][1] = s[n][2] = s[n][3] = 0.0f;
            const uint32_t rb = (uint32_t)((n * 8 + g) * KSTR_B);
#pragma unroll
            for (int t = 0; t < 4; t++) {
                const uint32_t co = rb + (uint32_t)((t * 16 + tig * 2) * 2);
                const uint32_t bh0 = *(const uint32_t*)(bufp + SM_KH + co);
                const uint32_t bh1 = *(const uint32_t*)(bufp + SM_KH + co + 16);
                const uint32_t bl0 = *(const uint32_t*)(bufp + SM_KL + co);
                const uint32_t bl1 = *(const uint32_t*)(bufp + SM_KL + co + 16);
                mma16816(s[n], qh[t], bh0, bh1);
                mma16816(s[n], ql[t], bh0, bh1);
                mma16816(s[n], qh[t], bl0, bl1);
            }
        }

        // ---- online softmax: rows r0=g, r1=g+8; reduce over quad lanes ----
        float rm0 = -INFINITY, rm1 = -INFINITY;
#pragma unroll
        for (int n = 0; n < 8; n++) {
            rm0 = fmaxf(rm0, fmaxf(s[n][0], s[n][1]));
            rm1 = fmaxf(rm1, fmaxf(s[n][2], s[n][3]));
        }
        rm0 = fmaxf(rm0, __shfl_xor_sync(0xffffffffu, rm0, 1));
        rm0 = fmaxf(rm0, __shfl_xor_sync(0xffffffffu, rm0, 2));
        rm1 = fmaxf(rm1, __shfl_xor_sync(0xffffffffu, rm1, 1));
        rm1 = fmaxf(rm1, __shfl_xor_sync(0xffffffffu, rm1, 2));

        const float mn0 = fmaxf(m0, rm0), mn1 = fmaxf(m1, rm1);
        const float c0 = fast_exp2(m0 - mn0), c1 = fast_exp2(m1 - mn1);
        m0 = mn0; m1 = mn1;
#pragma unroll
        for (int n = 0; n < 8; n++) {
            o[n][0] *= c0; o[n][1] *= c0;
            o[n][2] *= c1; o[n][3] *= c1;
        }
        float ps0 = 0.0f, ps1 = 0.0f;
#pragma unroll
        for (int n = 0; n < 8; n++) {
            s[n][0] = fast_exp2(s[n][0] - mn0);
            s[n][1] = fast_exp2(s[n][1] - mn0);
            s[n][2] = fast_exp2(s[n][2] - mn1);
            s[n][3] = fast_exp2(s[n][3] - mn1);
            ps0 += s[n][0] + s[n][1];
            ps1 += s[n][2] + s[n][3];
        }
        ps0 += __shfl_xor_sync(0xffffffffu, ps0, 1);
        ps0 += __shfl_xor_sync(0xffffffffu, ps0, 2);
        ps1 += __shfl_xor_sync(0xffffffffu, ps1, 1);
        ps1 += __shfl_xor_sync(0xffffffffu, ps1, 2);
        l0 = l0 * c0 + ps0;
        l1 = l1 * c1 + ps1;

        // ---- P -> A fragments (D layout == A layout; split hi/lo) ----
        uint32_t ph[4][4], pl[4][4];
#pragma unroll
        for (int t = 0; t < 4; t++) {
            split_pack(s[2 * t][0],     s[2 * t][1],     ph[t][0], pl[t][0]);
            split_pack(s[2 * t][2],     s[2 * t][3],     ph[t][1], pl[t][1]);
            split_pack(s[2 * t + 1][0], s[2 * t + 1][1], ph[t][2], pl[t][2]);
            split_pack(s[2 * t + 1][2], s[2 * t + 1][3], ph[t][3], pl[t][3]);
        }

        // ---- O += P V : 8 n-tiles (d) x 4 k-tiles (keys) x 3 combos ----
#pragma unroll
        for (int n = 0; n < 8; n++) {
            const uint32_t rb = (uint32_t)((n * 8 + g) * KSTR_B);
#pragma unroll
            for (int t = 0; t < 4; t++) {
                const uint32_t co = rb + (uint32_t)((t * 16 + tig * 2) * 2);
                const uint32_t vh0 = *(const uint32_t*)(bufp + SM_VH + co);
                const uint32_t vh1 = *(const uint32_t*)(bufp + SM_VH + co + 16);
                const uint32_t vl0 = *(const uint32_t*)(bufp + SM_VL + co);
                const uint32_t vl1 = *(const uint32_t*)(bufp + SM_VL + co + 16);
                mma16816(o[n], ph[t], vh0, vh1);
                mma16816(o[n], pl[t], vh0, vh1);
                mma16816(o[n], ph[t], vl0, vl1);
            }
        }
        __syncthreads();   // buf reads done before next iter's cp.async overwrite
    }

    // ---- epilogue ----
    const float inv0 = 1.0f / l0, inv1 = 1.0f / l1;
    const int q0 = qt * 64 + w * 16 + g;
    float* ob = out + (size_t)b * SEQ * HID + (size_t)h * HD;
#pragma unroll
    for (int n = 0; n < 8; n++) {
        float2 w0, w1;
        w0.x = o[n][0] * inv0; w0.y = o[n][1] * inv0;
        w1.x = o[n][2] * inv1; w1.y = o[n][3] * inv1;
        *(float2*)(ob + (size_t)q0 * HID + n * 8 + tig * 2)       = w0;
        *(float2*)(ob + (size_t)(q0 + 8) * HID + n * 8 + tig * 2) = w1;
    }
}

// ---------------------------------------------------------------------------
extern "C" void kernel_launch(void* const* d_in, const int* in_sizes, int n_in,
                              void* d_out, int out_size) {
    const float* x    = (const float*)d_in[0];
    const float* W    = (const float*)d_in[1];
    const float* bias = (const float*)d_in[2];
    float* out = (float*)d_out;

    cudaFuncSetAttribute(attn_mma,
                         cudaFuncAttributeMaxDynamicSharedMemorySize, ATTN_SMEM);

    qkv_gemm<<<dim3(NOUT / 128, (NBATCH * SEQ) / 128), 256>>>(x, W, bias);
    attn_mma<<<dim3(SEQ / 64, NBATCH * NHEAD), 128, ATTN_SMEM>>>(out);
}

// round 9
// speedup vs baseline: 2.2014x; 1.2142x over previous
#include <cuda_runtime.h>
#include <cuda_bf16.h>
#include <math.h>
#include <stdint.h>

#define SEQ    4096
#define HID    768
#define NHEAD  12
#define HD     64
#define NBATCH 2
#define NOUT   2304   // 3*HID

#define XELEMS (NBATCH * SEQ * HID)   // 6291456
#define WELEMS (NOUT * HID)           // 1769472

// Split-bf16 scratch: hi and lo halves of y = x@W^T + b.
// Q blocks pre-scaled by 1/8*log2(e). Q,K natural [s][d]; V transposed [d][s].
__device__ __nv_bfloat16 g_yh[NBATCH * SEQ * NOUT];
__device__ __nv_bfloat16 g_yl[NBATCH * SEQ * NOUT];
// Split-bf16 copies of the GEMM inputs.
__device__ __nv_bfloat16 g_xh[XELEMS], g_xl[XELEMS];
__device__ __nv_bfloat16 g_wh[WELEMS], g_wl[WELEMS];

__device__ __forceinline__ float fast_exp2(float x) {
    float y;
    asm("ex2.approx.f32 %0, %1;" : "=f"(y) : "f"(x));
    return y;
}

// split float pair into packed bf16x2 hi and lo (first elem = low 16 bits)
__device__ __forceinline__ void split_pack(float a, float b,
                                           uint32_t& hi, uint32_t& lo) {
    __nv_bfloat16 ah = __float2bfloat16(a);
    __nv_bfloat16 bh = __float2bfloat16(b);
    __nv_bfloat16 al = __float2bfloat16(a - __bfloat162float(ah));
    __nv_bfloat16 bl = __float2bfloat16(b - __bfloat162float(bh));
    hi = (uint32_t)__bfloat16_as_ushort(ah) | ((uint32_t)__bfloat16_as_ushort(bh) << 16);
    lo = (uint32_t)__bfloat16_as_ushort(al) | ((uint32_t)__bfloat16_as_ushort(bl) << 16);
}
__device__ __forceinline__ void split1(float a, __nv_bfloat16& h, __nv_bfloat16& l) {
    h = __float2bfloat16(a);
    l = __float2bfloat16(a - __bfloat162float(h));
}

// m16n8k16 bf16 MMA, D/C fp32 in-place accumulate
__device__ __forceinline__ void mma16816(float* d, const uint32_t* a,
                                         uint32_t b0, uint32_t b1) {
    asm volatile(
        "mma.sync.aligned.m16n8k16.row.col.f32.bf16.bf16.f32 "
        "{%0,%1,%2,%3}, {%4,%5,%6,%7}, {%8,%9}, {%0,%1,%2,%3};"
        : "+f"(d[0]), "+f"(d[1]), "+f"(d[2]), "+f"(d[3])
        : "r"(a[0]), "r"(a[1]), "r"(a[2]), "r"(a[3]), "r"(b0), "r"(b1));
}

__device__ __forceinline__ uint32_t smem_u32(const void* p) {
    uint32_t a;
    asm("{ .reg .u64 t; cvta.to.shared.u64 t, %1; cvt.u32.u64 %0, t; }"
        : "=r"(a) : "l"(p));
    return a;
}
#define CP16(dst, src) \
    asm volatile("cp.async.cg.shared.global [%0], [%1], 16;" \
                 :: "r"(dst), "l"(src) : "memory")
#define CP_COMMIT() asm volatile("cp.async.commit_group;" ::: "memory")
#define CP_WAIT1()  asm volatile("cp.async.wait_group 1;" ::: "memory")
#define CP_WAIT0()  asm volatile("cp.async.wait_group 0;" ::: "memory")

// ---------------------------------------------------------------------------
// Input splitter: X, W fp32 -> bf16 hi/lo pairs. 1 thread per 4 elements.
// ---------------------------------------------------------------------------
__global__ __launch_bounds__(256) void split_inputs(const float* __restrict__ X,
                                                    const float* __restrict__ W) {
    const int i4 = blockIdx.x * blockDim.x + threadIdx.x;
    const int nx4 = XELEMS / 4;
    const int nw4 = WELEMS / 4;
    if (i4 < nx4) {
        const float4 v = ((const float4*)X)[i4];
        uint32_t h0, l0, h1, l1;
        split_pack(v.x, v.y, h0, l0);
        split_pack(v.z, v.w, h1, l1);
        uint2 hv; hv.x = h0; hv.y = h1;
        uint2 lv; lv.x = l0; lv.y = l1;
        ((uint2*)g_xh)[i4] = hv;
        ((uint2*)g_xl)[i4] = lv;
    } else if (i4 < nx4 + nw4) {
        const int j = i4 - nx4;
        const float4 v = ((const float4*)W)[j];
        uint32_t h0, l0, h1, l1;
        split_pack(v.x, v.y, h0, l0);
        split_pack(v.z, v.w, h1, l1);
        uint2 hv; hv.x = h0; hv.y = h1;
        uint2 lv; lv.x = l0; lv.y = l1;
        ((uint2*)g_wh)[j] = hv;
        ((uint2*)g_wl)[j] = lv;
    }
}

// ---------------------------------------------------------------------------
// Tensor-core QKV GEMM: y[m][n] = sum_k X[m][k]*W[n][k] + b[n], split-bf16 3-pass.
// Tile 128x128, BK=64, 256 threads (8 warps; warp = 32 m x 64 n).
// smem row stride 144 B (conflict-free fragment LDS: bank = 4g + tig).
// Epilogue: bias + Q-scale + split-bf16 + V-transpose scatter (as before).
// ---------------------------------------------------------------------------
#define G_AH 0
#define G_AL 18432
#define G_BH 36864
#define G_BL 55296
#define GBUF 73728
#define GEMM_SMEM (2 * GBUF)   // 147456

__global__ __launch_bounds__(256) void qkv_gemm_mma(const float* __restrict__ bias) {
    extern __shared__ __align__(16) unsigned char smg[];
    const uint32_t sb = smem_u32(smg);

    const int tid  = threadIdx.x;
    const int wid  = tid >> 5;
    const int lane = tid & 31;
    const int g    = lane >> 2;
    const int tig  = lane & 3;
    const int wr   = wid >> 1;      // 0..3: m block of 32
    const int wc   = wid & 1;       // 0..1: n block of 64
    const int mBase = blockIdx.y * 128;
    const int nBase = blockIdx.x * 128;

    const char* Xh8 = (const char*)g_xh;
    const char* Xl8 = (const char*)g_xl;
    const char* Wh8 = (const char*)g_wh;
    const char* Wl8 = (const char*)g_wl;

    // cp.async mapping: per array 1024 segs of 16B; thread does 4.
    int cr[4], cc[4];
#pragma unroll
    for (int i = 0; i < 4; i++) {
        const int seg = tid + i * 256;
        cr[i] = seg >> 3;            // row 0..127
        cc[i] = (seg & 7) * 16;      // byte col 0..112
    }

#define GCOPY(kcc, bufb) do {                                                  \
    const uint32_t _sb = (bufb);                                               \
_Pragma("unroll")                                                              \
    for (int i = 0; i < 4; i++) {                                              \
        const uint32_t so = (uint32_t)(cr[i] * 144 + cc[i]);                   \
        const size_t ga = (size_t)(mBase + cr[i]) * 1536 + (kcc) * 128 + cc[i];\
        const size_t gb = (size_t)(nBase + cr[i]) * 1536 + (kcc) * 128 + cc[i];\
        CP16(_sb + G_AH + so, Xh8 + ga);                                       \
        CP16(_sb + G_AL + so, Xl8 + ga);                                       \
        CP16(_sb + G_BH + so, Wh8 + gb);                                       \
        CP16(_sb + G_BL + so, Wl8 + gb);                                       \
    }                                                                          \
} while (0)

    float acc[2][8][4];
#pragma unroll
    for (int mi = 0; mi < 2; mi++)
#pragma unroll
        for (int ni = 0; ni < 8; ni++)
#pragma unroll
            for (int j = 0; j < 4; j++) acc[mi][ni][j] = 0.0f;

    GCOPY(0, sb);
    CP_COMMIT();

    for (int kc = 0; kc < 12; kc++) {
        if (kc < 11) {
            GCOPY(kc + 1, sb + (uint32_t)((kc + 1) & 1) * GBUF);
            CP_COMMIT();
            CP_WAIT1();
        } else {
            CP_WAIT0();
        }
        __syncthreads();

        const unsigned char* bufp = smg + (kc & 1) * GBUF;

#pragma unroll
        for (int ks = 0; ks < 4; ks++) {
            const uint32_t co = (uint32_t)((ks * 16 + tig * 2) * 2);
            uint32_t ah[2][4], al[2][4];
#pragma unroll
            for (int mi = 0; mi < 2; mi++) {
                const uint32_t r0 = (uint32_t)((wr * 32 + mi * 16 + g) * 144);
                ah[mi][0] = *(const uint32_t*)(bufp + G_AH + r0 + co);
                ah[mi][1] = *(const uint32_t*)(bufp + G_AH + r0 + 8 * 144 + co);
                ah[mi][2] = *(const uint32_t*)(bufp + G_AH + r0 + co + 16);
                ah[mi][3] = *(const uint32_t*)(bufp + G_AH + r0 + 8 * 144 + co + 16);
                al[mi][0] = *(const uint32_t*)(bufp + G_AL + r0 + co);
                al[mi][1] = *(const uint32_t*)(bufp + G_AL + r0 + 8 * 144 + co);
                al[mi][2] = *(const uint32_t*)(bufp + G_AL + r0 + co + 16);
                al[mi][3] = *(const uint32_t*)(bufp + G_AL + r0 + 8 * 144 + co + 16);
            }
#pragma unroll
            for (int ni = 0; ni < 8; ni++) {
                const uint32_t nr = (uint32_t)((wc * 64 + ni * 8 + g) * 144);
                const uint32_t bh0 = *(const uint32_t*)(bufp + G_BH + nr + co);
                const uint32_t bh1 = *(const uint32_t*)(bufp + G_BH + nr + co + 16);
                const uint32_t bl0 = *(const uint32_t*)(bufp + G_BL + nr + co);
                const uint32_t bl1 = *(const uint32_t*)(bufp + G_BL + nr + co + 16);
#pragma unroll
                for (int mi = 0; mi < 2; mi++) {
                    mma16816(acc[mi][ni], ah[mi], bh0, bh1);
                    mma16816(acc[mi][ni], al[mi], bh0, bh1);
                    mma16816(acc[mi][ni], ah[mi], bl0, bl1);
                }
            }
        }
        __syncthreads();
    }

    // ---- epilogue: bias + scale + split + scatter ----
    const float SC = 0.125f * 1.4426950408889634f;   // Q blocks only
#pragma unroll
    for (int mi = 0; mi < 2; mi++) {
#pragma unroll
        for (int ni = 0; ni < 8; ni++) {
            const int n = nBase + wc * 64 + ni * 8 + tig * 2;
            const float bx = __ldg(&bias[n]);
            const float by = __ldg(&bias[n + 1]);
#pragma unroll
            for (int hh2 = 0; hh2 < 2; hh2++) {
                const int row = mBase + wr * 32 + mi * 16 + g + hh2 * 8;
                float v0 = acc[mi][ni][hh2 * 2 + 0] + bx;
                float v1 = acc[mi][ni][hh2 * 2 + 1] + by;
                const int s = row & 4095;
                const size_t bb = (size_t)(row >> 12) * (SEQ * (size_t)NOUT);
                const uint32_t fb = (uint32_t)s * NOUT + n;
                const uint32_t gB = fb >> 18;            // 0..35 = h*3 + t
                const uint32_t t3 = gB % 3u;
                if (t3 != 2u) {
                    if (t3 == 0u) { v0 *= SC; v1 *= SC; }
                    uint32_t hi, lo;
                    split_pack(v0, v1, hi, lo);
                    *(uint32_t*)(g_yh + bb + fb) = hi;
                    *(uint32_t*)(g_yl + bb + fb) = lo;
                } else {
                    const uint32_t o18 = fb & 0x3FFFFu;
                    const uint32_t d0  = o18 & 63u;
                    const uint32_t s2  = o18 >> 6;
                    __nv_bfloat16* vh = g_yh + bb + (size_t)gB * 262144;
                    __nv_bfloat16* vl = g_yl + bb + (size_t)gB * 262144;
                    __nv_bfloat16 hh, ll;
                    split1(v0, hh, ll);
                    vh[(size_t)d0 * SEQ + s2] = hh; vl[(size_t)d0 * SEQ + s2] = ll;
                    split1(v1, hh, ll);
                    vh[(size_t)(d0 + 1) * SEQ + s2] = hh;
                    vl[(size_t)(d0 + 1) * SEQ + s2] = ll;
                }
            }
        }
    }
}

// ---------------------------------------------------------------------------
// FA2-style flash attention, mma.sync bf16 split hi/lo, cp.async double-buffer.
// (unchanged from round 8 passing version)
// ---------------------------------------------------------------------------
#define KSTR_B 144
#define SM_KH  0
#define SM_KL  9216
#define SM_VH  18432
#define SM_VL  27648
#define BUFSZ  36864
#define ATTN_SMEM (2 * BUFSZ)

__global__ __launch_bounds__(128) void attn_mma(float* __restrict__ out) {
    extern __shared__ __align__(16) unsigned char smraw[];
    const uint32_t sb = smem_u32(smraw);

    const int tid  = threadIdx.x;
    const int w    = tid >> 5;
    const int lane = tid & 31;
    const int g    = lane >> 2;
    const int tig  = lane & 3;

    const int qt = blockIdx.x;
    const int b  = blockIdx.y / NHEAD;
    const int h  = blockIdx.y % NHEAD;

    const size_t boff = (size_t)b * (SEQ * (size_t)NOUT) + (size_t)h * (3 * SEQ * HD);
    const __nv_bfloat16* Qh16 = g_yh + boff;
    const __nv_bfloat16* Ql16 = g_yl + boff;
    const char* Kh8 = (const char*)(g_yh + boff + SEQ * HD);
    const char* Kl8 = (const char*)(g_yl + boff + SEQ * HD);
    const char* Vh8 = (const char*)(g_yh + boff + 2 * SEQ * HD);
    const char* Vl8 = (const char*)(g_yl + boff + 2 * SEQ * HD);

    const int rowbase = qt * 64 + w * 16;

    int cr[4], cc[4];
#pragma unroll
    for (int i = 0; i < 4; i++) {
        const int seg = tid + i * 128;
        cr[i] = seg >> 3;
        cc[i] = (seg & 7) * 16;
    }

#define COPY_CHUNK(kcc, bufbase) do {                                          \
    const size_t kofsK = (size_t)(kcc) * 8192;                                 \
    const size_t kofsV = (size_t)(kcc) * 128;                                  \
    const uint32_t _sb = (bufbase);                                            \
_Pragma("unroll")                                                              \
    for (int i = 0; i < 4; i++) {                                              \
        const uint32_t so = (uint32_t)(cr[i] * KSTR_B + cc[i]);                \
        const size_t   gk = kofsK + (size_t)cr[i] * 128 + cc[i];               \
        const size_t   gv = (size_t)cr[i] * (SEQ * 2) + kofsV + cc[i];         \
        CP16(_sb + SM_KH + so, Kh8 + gk);                                      \
        CP16(_sb + SM_KL + so, Kl8 + gk);                                      \
        CP16(_sb + SM_VH + so, Vh8 + gv);                                      \
        CP16(_sb + SM_VL + so, Vl8 + gv);                                      \
    }                                                                          \
} while (0)

    uint32_t qh[4][4], ql[4][4];
#pragma unroll
    for (int kt = 0; kt < 4; kt++)
#pragma unroll
        for (int rr = 0; rr < 2; rr++)
#pragma unroll
            for (int cc2 = 0; cc2 < 2; cc2++) {
                const size_t eo = (size_t)(rowbase + g + rr * 8) * HD
                                + kt * 16 + tig * 2 + cc2 * 8;
                qh[kt][rr + cc2 * 2] = *(const uint32_t*)(Qh16 + eo);
                ql[kt][rr + cc2 * 2] = *(const uint32_t*)(Ql16 + eo);
            }

    float o[8][4];
#pragma unroll
    for (int n = 0; n < 8; n++)
#pragma unroll
        for (int j = 0; j < 4; j++) o[n][j] = 0.0f;
    float m0 = -INFINITY, m1 = -INFINITY, l0 = 0.0f, l1 = 0.0f;

    COPY_CHUNK(0, sb);
    CP_COMMIT();

    for (int kc = 0; kc < 64; kc++) {
        if (kc < 63) {
            COPY_CHUNK(kc + 1, sb + (uint32_t)((kc + 1) & 1) * BUFSZ);
            CP_COMMIT();
            CP_WAIT1();
        } else {
            CP_WAIT0();
        }
        __syncthreads();

        const unsigned char* bufp = smraw + (kc & 1) * BUFSZ;

        float s[8][4];
#pragma unroll
        for (int n = 0; n < 8; n++) {
            s[n][0] = s[n][1] = s[n][2] = s[n][3] = 0.0f;
            const uint32_t rb = (uint32_t)((n * 8 + g) * KSTR_B);
#pragma unroll
            for (int t = 0; t < 4; t++) {
                const uint32_t co = rb + (uint32_t)((t * 16 + tig * 2) * 2);
                const uint32_t bh0 = *(const uint32_t*)(bufp + SM_KH + co);
                const uint32_t bh1 = *(const uint32_t*)(bufp + SM_KH + co + 16);
                const uint32_t bl0 = *(const uint32_t*)(bufp + SM_KL + co);
                const uint32_t bl1 = *(const uint32_t*)(bufp + SM_KL + co + 16);
                mma16816(s[n], qh[t], bh0, bh1);
                mma16816(s[n], ql[t], bh0, bh1);
                mma16816(s[n], qh[t], bl0, bl1);
            }
        }

        float rm0 = -INFINITY, rm1 = -INFINITY;
#pragma unroll
        for (int n = 0; n < 8; n++) {
            rm0 = fmaxf(rm0, fmaxf(s[n][0], s[n][1]));
            rm1 = fmaxf(rm1, fmaxf(s[n][2], s[n][3]));
        }
        rm0 = fmaxf(rm0, __shfl_xor_sync(0xffffffffu, rm0, 1));
        rm0 = fmaxf(rm0, __shfl_xor_sync(0xffffffffu, rm0, 2));
        rm1 = fmaxf(rm1, __shfl_xor_sync(0xffffffffu, rm1, 1));
        rm1 = fmaxf(rm1, __shfl_xor_sync(0xffffffffu, rm1, 2));

        const float mn0 = fmaxf(m0, rm0), mn1 = fmaxf(m1, rm1);
        const float c0 = fast_exp2(m0 - mn0), c1 = fast_exp2(m1 - mn1);
        m0 = mn0; m1 = mn1;
#pragma unroll
        for (int n = 0; n < 8; n++) {
            o[n][0] *= c0; o[n][1] *= c0;
            o[n][2] *= c1; o[n][3] *= c1;
        }
        float ps0 = 0.0f, ps1 = 0.0f;
#pragma unroll
        for (int n = 0; n < 8; n++) {
            s[n][0] = fast_exp2(s[n][0] - mn0);
            s[n][1] = fast_exp2(s[n][1] - mn0);
            s[n][2] = fast_exp2(s[n][2] - mn1);
            s[n][3] = fast_exp2(s[n][3] - mn1);
            ps0 += s[n][0] + s[n][1];
            ps1 += s[n][2] + s[n][3];
        }
        ps0 += __shfl_xor_sync(0xffffffffu, ps0, 1);
        ps0 += __shfl_xor_sync(0xffffffffu, ps0, 2);
        ps1 += __shfl_xor_sync(0xffffffffu, ps1, 1);
        ps1 += __shfl_xor_sync(0xffffffffu, ps1, 2);
        l0 = l0 * c0 + ps0;
        l1 = l1 * c1 + ps1;

        uint32_t ph[4][4], pl[4][4];
#pragma unroll
        for (int t = 0; t < 4; t++) {
            split_pack(s[2 * t][0],     s[2 * t][1],     ph[t][0], pl[t][0]);
            split_pack(s[2 * t][2],     s[2 * t][3],     ph[t][1], pl[t][1]);
            split_pack(s[2 * t + 1][0], s[2 * t + 1][1], ph[t][2], pl[t][2]);
            split_pack(s[2 * t + 1][2], s[2 * t + 1][3], ph[t][3], pl[t][3]);
        }

#pragma unroll
        for (int n = 0; n < 8; n++) {
            const uint32_t rb = (uint32_t)((n * 8 + g) * KSTR_B);
#pragma unroll
            for (int t = 0; t < 4; t++) {
                const uint32_t co = rb + (uint32_t)((t * 16 + tig * 2) * 2);
                const uint32_t vh0 = *(const uint32_t*)(bufp + SM_VH + co);
                const uint32_t vh1 = *(const uint32_t*)(bufp + SM_VH + co + 16);
                const uint32_t vl0 = *(const uint32_t*)(bufp + SM_VL + co);
                const uint32_t vl1 = *(const uint32_t*)(bufp + SM_VL + co + 16);
                mma16816(o[n], ph[t], vh0, vh1);
                mma16816(o[n], pl[t], vh0, vh1);
                mma16816(o[n], ph[t], vl0, vl1);
            }
        }
        __syncthreads();
    }

    const float inv0 = 1.0f / l0, inv1 = 1.0f / l1;
    const int q0 = qt * 64 + w * 16 + g;
    float* ob = out + (size_t)b * SEQ * HID + (size_t)h * HD;
#pragma unroll
    for (int n = 0; n < 8; n++) {
        float2 w0, w1;
        w0.x = o[n][0] * inv0; w0.y = o[n][1] * inv0;
        w1.x = o[n][2] * inv1; w1.y = o[n][3] * inv1;
        *(float2*)(ob + (size_t)q0 * HID + n * 8 + tig * 2)       = w0;
        *(float2*)(ob + (size_t)(q0 + 8) * HID + n * 8 + tig * 2) = w1;
    }
}

// ---------------------------------------------------------------------------
extern "C" void kernel_launch(void* const* d_in, const int* in_sizes, int n_in,
                              void* d_out, int out_size) {
    const float* x    = (const float*)d_in[0];
    const float* W    = (const float*)d_in[1];
    const float* bias = (const float*)d_in[2];
    float* out = (float*)d_out;

    cudaFuncSetAttribute(qkv_gemm_mma,
                         cudaFuncAttributeMaxDynamicSharedMemorySize, GEMM_SMEM);
    cudaFuncSetAttribute(attn_mma,
                         cudaFuncAttributeMaxDynamicSharedMemorySize, ATTN_SMEM);

    const int splitBlocks = (XELEMS / 4 + WELEMS / 4 + 255) / 256;
    split_inputs<<<splitBlocks, 256>>>(x, W);
    qkv_gemm_mma<<<dim3(NOUT / 128, (NBATCH * SEQ) / 128), 256, GEMM_SMEM>>>(bias);
    attn_mma<<<dim3(SEQ / 64, NBATCH * NHEAD), 128, ATTN_SMEM>>>(out);
}

// round 10
// speedup vs baseline: 2.2110x; 1.0044x over previous
#include <cuda_runtime.h>
#include <cuda_bf16.h>
#include <math.h>
#include <stdint.h>

#define SEQ    4096
#define HID    768
#define NHEAD  12
#define HD     64
#define NBATCH 2
#define NOUT   2304   // 3*HID

#define XELEMS (NBATCH * SEQ * HID)   // 6291456
#define WELEMS (NOUT * HID)           // 1769472

// Split-bf16 scratch: hi and lo halves of y = x@W^T + b.
// Q blocks pre-scaled by 1/8*log2(e). Q,K natural [s][d]; V transposed [d][s].
__device__ __nv_bfloat16 g_yh[NBATCH * SEQ * NOUT];
__device__ __nv_bfloat16 g_yl[NBATCH * SEQ * NOUT];
// Split-bf16 copies of the GEMM inputs.
__device__ __nv_bfloat16 g_xh[XELEMS], g_xl[XELEMS];
__device__ __nv_bfloat16 g_wh[WELEMS], g_wl[WELEMS];

__device__ __forceinline__ float fast_exp2(float x) {
    float y;
    asm("ex2.approx.f32 %0, %1;" : "=f"(y) : "f"(x));
    return y;
}

// split float pair into packed bf16x2 hi and lo (first elem = low 16 bits)
__device__ __forceinline__ void split_pack(float a, float b,
                                           uint32_t& hi, uint32_t& lo) {
    __nv_bfloat16 ah = __float2bfloat16(a);
    __nv_bfloat16 bh = __float2bfloat16(b);
    __nv_bfloat16 al = __float2bfloat16(a - __bfloat162float(ah));
    __nv_bfloat16 bl = __float2bfloat16(b - __bfloat162float(bh));
    hi = (uint32_t)__bfloat16_as_ushort(ah) | ((uint32_t)__bfloat16_as_ushort(bh) << 16);
    lo = (uint32_t)__bfloat16_as_ushort(al) | ((uint32_t)__bfloat16_as_ushort(bl) << 16);
}
__device__ __forceinline__ void split1(float a, __nv_bfloat16& h, __nv_bfloat16& l) {
    h = __float2bfloat16(a);
    l = __float2bfloat16(a - __bfloat162float(h));
}

// m16n8k16 bf16 MMA, D/C fp32 in-place accumulate
__device__ __forceinline__ void mma16816(float* d, const uint32_t* a,
                                         uint32_t b0, uint32_t b1) {
    asm volatile(
        "mma.sync.aligned.m16n8k16.row.col.f32.bf16.bf16.f32 "
        "{%0,%1,%2,%3}, {%4,%5,%6,%7}, {%8,%9}, {%0,%1,%2,%3};"
        : "+f"(d[0]), "+f"(d[1]), "+f"(d[2]), "+f"(d[3])
        : "r"(a[0]), "r"(a[1]), "r"(a[2]), "r"(a[3]), "r"(b0), "r"(b1));
}

__device__ __forceinline__ uint32_t smem_u32(const void* p) {
    uint32_t a;
    asm("{ .reg .u64 t; cvta.to.shared.u64 t, %1; cvt.u32.u64 %0, t; }"
        : "=r"(a) : "l"(p));
    return a;
}
#define CP16(dst, src) \
    asm volatile("cp.async.cg.shared.global [%0], [%1], 16;" \
                 :: "r"(dst), "l"(src) : "memory")
#define CP_COMMIT() asm volatile("cp.async.commit_group;" ::: "memory")
#define CP_WAIT1()  asm volatile("cp.async.wait_group 1;" ::: "memory")
#define CP_WAIT0()  asm volatile("cp.async.wait_group 0;" ::: "memory")

// ---------------------------------------------------------------------------
// Input splitter: X, W fp32 -> bf16 hi/lo pairs. 1 thread per 4 elements.
// ---------------------------------------------------------------------------
__global__ __launch_bounds__(256) void split_inputs(const float* __restrict__ X,
                                                    const float* __restrict__ W) {
    const int i4 = blockIdx.x * blockDim.x + threadIdx.x;
    const int nx4 = XELEMS / 4;
    const int nw4 = WELEMS / 4;
    if (i4 < nx4) {
        const float4 v = ((const float4*)X)[i4];
        uint32_t h0, l0, h1, l1;
        split_pack(v.x, v.y, h0, l0);
        split_pack(v.z, v.w, h1, l1);
        uint2 hv; hv.x = h0; hv.y = h1;
        uint2 lv; lv.x = l0; lv.y = l1;
        ((uint2*)g_xh)[i4] = hv;
        ((uint2*)g_xl)[i4] = lv;
    } else if (i4 < nx4 + nw4) {
        const int j = i4 - nx4;
        const float4 v = ((const float4*)W)[j];
        uint32_t h0, l0, h1, l1;
        split_pack(v.x, v.y, h0, l0);
        split_pack(v.z, v.w, h1, l1);
        uint2 hv; hv.x = h0; hv.y = h1;
        uint2 lv; lv.x = l0; lv.y = l1;
        ((uint2*)g_wh)[j] = hv;
        ((uint2*)g_wl)[j] = lv;
    }
}

// ---------------------------------------------------------------------------
// Tensor-core QKV GEMM: y[m][n] = sum_k X[m][k]*W[n][k] + b[n], split-bf16 3-pass.
// Tile 128x128, BK=64, 256 threads (8 warps; warp = 32 m x 64 n).
// smem row stride 144 B (conflict-free fragment LDS: bank = 4g + tig).
// Epilogue: bias + Q-scale + split-bf16 + V-transpose scatter (as before).
// ---------------------------------------------------------------------------
#define G_AH 0
#define G_AL 18432
#define G_BH 36864
#define G_BL 55296
#define GBUF 73728
#define GEMM_SMEM (2 * GBUF)   // 147456

__global__ __launch_bounds__(256) void qkv_gemm_mma(const float* __restrict__ bias) {
    extern __shared__ __align__(16) unsigned char smg[];
    const uint32_t sb = smem_u32(smg);

    const int tid  = threadIdx.x;
    const int wid  = tid >> 5;
    const int lane = tid & 31;
    const int g    = lane >> 2;
    const int tig  = lane & 3;
    const int wr   = wid >> 1;      // 0..3: m block of 32
    const int wc   = wid & 1;       // 0..1: n block of 64
    const int mBase = blockIdx.y * 128;
    const int nBase = blockIdx.x * 128;

    const char* Xh8 = (const char*)g_xh;
    const char* Xl8 = (const char*)g_xl;
    const char* Wh8 = (const char*)g_wh;
    const char* Wl8 = (const char*)g_wl;

    // cp.async mapping: per array 1024 segs of 16B; thread does 4.
    int cr[4], cc[4];
#pragma unroll
    for (int i = 0; i < 4; i++) {
        const int seg = tid + i * 256;
        cr[i] = seg >> 3;            // row 0..127
        cc[i] = (seg & 7) * 16;      // byte col 0..112
    }

#define GCOPY(kcc, bufb) do {                                                  \
    const uint32_t _sb = (bufb);                                               \
_Pragma("unroll")                                                              \
    for (int i = 0; i < 4; i++) {                                              \
        const uint32_t so = (uint32_t)(cr[i] * 144 + cc[i]);                   \
        const size_t ga = (size_t)(mBase + cr[i]) * 1536 + (kcc) * 128 + cc[i];\
        const size_t gb = (size_t)(nBase + cr[i]) * 1536 + (kcc) * 128 + cc[i];\
        CP16(_sb + G_AH + so, Xh8 + ga);                                       \
        CP16(_sb + G_AL + so, Xl8 + ga);                                       \
        CP16(_sb + G_BH + so, Wh8 + gb);                                       \
        CP16(_sb + G_BL + so, Wl8 + gb);                                       \
    }                                                                          \
} while (0)

    float acc[2][8][4];
#pragma unroll
    for (int mi = 0; mi < 2; mi++)
#pragma unroll
        for (int ni = 0; ni < 8; ni++)
#pragma unroll
            for (int j = 0; j < 4; j++) acc[mi][ni][j] = 0.0f;

    GCOPY(0, sb);
    CP_COMMIT();

    for (int kc = 0; kc < 12; kc++) {
        if (kc < 11) {
            GCOPY(kc + 1, sb + (uint32_t)((kc + 1) & 1) * GBUF);
            CP_COMMIT();
            CP_WAIT1();
        } else {
            CP_WAIT0();
        }
        __syncthreads();

        const unsigned char* bufp = smg + (kc & 1) * GBUF;

#pragma unroll
        for (int ks = 0; ks < 4; ks++) {
            const uint32_t co = (uint32_t)((ks * 16 + tig * 2) * 2);
            uint32_t ah[2][4], al[2][4];
#pragma unroll
            for (int mi = 0; mi < 2; mi++) {
                const uint32_t r0 = (uint32_t)((wr * 32 + mi * 16 + g) * 144);
                ah[mi][0] = *(const uint32_t*)(bufp + G_AH + r0 + co);
                ah[mi][1] = *(const uint32_t*)(bufp + G_AH + r0 + 8 * 144 + co);
                ah[mi][2] = *(const uint32_t*)(bufp + G_AH + r0 + co + 16);
                ah[mi][3] = *(const uint32_t*)(bufp + G_AH + r0 + 8 * 144 + co + 16);
                al[mi][0] = *(const uint32_t*)(bufp + G_AL + r0 + co);
                al[mi][1] = *(const uint32_t*)(bufp + G_AL + r0 + 8 * 144 + co);
                al[mi][2] = *(const uint32_t*)(bufp + G_AL + r0 + co + 16);
                al[mi][3] = *(const uint32_t*)(bufp + G_AL + r0 + 8 * 144 + co + 16);
            }
#pragma unroll
            for (int ni = 0; ni < 8; ni++) {
                const uint32_t nr = (uint32_t)((wc * 64 + ni * 8 + g) * 144);
                const uint32_t bh0 = *(const uint32_t*)(bufp + G_BH + nr + co);
                const uint32_t bh1 = *(const uint32_t*)(bufp + G_BH + nr + co + 16);
                const uint32_t bl0 = *(const uint32_t*)(bufp + G_BL + nr + co);
                const uint32_t bl1 = *(const uint32_t*)(bufp + G_BL + nr + co + 16);
#pragma unroll
                for (int mi = 0; mi < 2; mi++) {
                    mma16816(acc[mi][ni], ah[mi], bh0, bh1);
                    mma16816(acc[mi][ni], al[mi], bh0, bh1);
                    mma16816(acc[mi][ni], ah[mi], bl0, bl1);
                }
            }
        }
        __syncthreads();
    }

    // ---- epilogue: bias + scale + split + scatter ----
    const float SC = 0.125f * 1.4426950408889634f;   // Q blocks only
#pragma unroll
    for (int mi = 0; mi < 2; mi++) {
#pragma unroll
        for (int ni = 0; ni < 8; ni++) {
            const int n = nBase + wc * 64 + ni * 8 + tig * 2;
            const float bx = __ldg(&bias[n]);
            const float by = __ldg(&bias[n + 1]);
#pragma unroll
            for (int hh2 = 0; hh2 < 2; hh2++) {
                const int row = mBase + wr * 32 + mi * 16 + g + hh2 * 8;
                float v0 = acc[mi][ni][hh2 * 2 + 0] + bx;
                float v1 = acc[mi][ni][hh2 * 2 + 1] + by;
                const int s = row & 4095;
                const size_t bb = (size_t)(row >> 12) * (SEQ * (size_t)NOUT);
                const uint32_t fb = (uint32_t)s * NOUT + n;
                const uint32_t gB = fb >> 18;            // 0..35 = h*3 + t
                const uint32_t t3 = gB % 3u;
                if (t3 != 2u) {
                    if (t3 == 0u) { v0 *= SC; v1 *= SC; }
                    uint32_t hi, lo;
                    split_pack(v0, v1, hi, lo);
                    *(uint32_t*)(g_yh + bb + fb) = hi;
                    *(uint32_t*)(g_yl + bb + fb) = lo;
                } else {
                    const uint32_t o18 = fb & 0x3FFFFu;
                    const uint32_t d0  = o18 & 63u;
                    const uint32_t s2  = o18 >> 6;
                    __nv_bfloat16* vh = g_yh + bb + (size_t)gB * 262144;
                    __nv_bfloat16* vl = g_yl + bb + (size_t)gB * 262144;
                    __nv_bfloat16 hh, ll;
                    split1(v0, hh, ll);
                    vh[(size_t)d0 * SEQ + s2] = hh; vl[(size_t)d0 * SEQ + s2] = ll;
                    split1(v1, hh, ll);
                    vh[(size_t)(d0 + 1) * SEQ + s2] = hh;
                    vl[(size_t)(d0 + 1) * SEQ + s2] = ll;
                }
            }
        }
    }
}

// ---------------------------------------------------------------------------
// FA2-style flash attention, mma.sync bf16 split hi/lo, cp.async double-buffer.
// (unchanged from round 8 passing version)
// ---------------------------------------------------------------------------
#define KSTR_B 144
#define SM_KH  0
#define SM_KL  9216
#define SM_VH  18432
#define SM_VL  27648
#define BUFSZ  36864
#define ATTN_SMEM (2 * BUFSZ)

__global__ __launch_bounds__(128) void attn_mma(float* __restrict__ out) {
    extern __shared__ __align__(16) unsigned char smraw[];
    const uint32_t sb = smem_u32(smraw);

    const int tid  = threadIdx.x;
    const int w    = tid >> 5;
    const int lane = tid & 31;
    const int g    = lane >> 2;
    const int tig  = lane & 3;

    const int qt = blockIdx.x;
    const int b  = blockIdx.y / NHEAD;
    const int h  = blockIdx.y % NHEAD;

    const size_t boff = (size_t)b * (SEQ * (size_t)NOUT) + (size_t)h * (3 * SEQ * HD);
    const __nv_bfloat16* Qh16 = g_yh + boff;
    const __nv_bfloat16* Ql16 = g_yl + boff;
    const char* Kh8 = (const char*)(g_yh + boff + SEQ * HD);
    const char* Kl8 = (const char*)(g_yl + boff + SEQ * HD);
    const char* Vh8 = (const char*)(g_yh + boff + 2 * SEQ * HD);
    const char* Vl8 = (const char*)(g_yl + boff + 2 * SEQ * HD);

    const int rowbase = qt * 64 + w * 16;

    int cr[4], cc[4];
#pragma unroll
    for (int i = 0; i < 4; i++) {
        const int seg = tid + i * 128;
        cr[i] = seg >> 3;
        cc[i] = (seg & 7) * 16;
    }

#define COPY_CHUNK(kcc, bufbase) do {                                          \
    const size_t kofsK = (size_t)(kcc) * 8192;                                 \
    const size_t kofsV = (size_t)(kcc) * 128;                                  \
    const uint32_t _sb = (bufbase);                                            \
_Pragma("unroll")                                                              \
    for (int i = 0; i < 4; i++) {                                              \
        const uint32_t so = (uint32_t)(cr[i] * KSTR_B + cc[i]);                \
        const size_t   gk = kofsK + (size_t)cr[i] * 128 + cc[i];               \
        const size_t   gv = (size_t)cr[i] * (SEQ * 2) + kofsV + cc[i];         \
        CP16(_sb + SM_KH + so, Kh8 + gk);                                      \
        CP16(_sb + SM_KL + so, Kl8 + gk);                                      \
        CP16(_sb + SM_VH + so, Vh8 + gv);                                      \
        CP16(_sb + SM_VL + so, Vl8 + gv);                                      \
    }                                                                          \
} while (0)

    uint32_t qh[4][4], ql[4][4];
#pragma unroll
    for (int kt = 0; kt < 4; kt++)
#pragma unroll
        for (int rr = 0; rr < 2; rr++)
#pragma unroll
            for (int cc2 = 0; cc2 < 2; cc2++) {
                const size_t eo = (size_t)(rowbase + g + rr * 8) * HD
                                + kt * 16 + tig * 2 + cc2 * 8;
                qh[kt][rr + cc2 * 2] = *(const uint32_t*)(Qh16 + eo);
                ql[kt][rr + cc2 * 2] = *(const uint32_t*)(Ql16 + eo);
            }

    float o[8][4];
#pragma unroll
    for (int n = 0; n < 8; n++)
#pragma unroll
        for (int j = 0; j < 4; j++) o[n][j] = 0.0f;
    float m0 = -INFINITY, m1 = -INFINITY, l0 = 0.0f, l1 = 0.0f;

    COPY_CHUNK(0, sb);
    CP_COMMIT();

    for (int kc = 0; kc < 64; kc++) {
        if (kc < 63) {
            COPY_CHUNK(kc + 1, sb + (uint32_t)((kc + 1) & 1) * BUFSZ);
            CP_COMMIT();
            CP_WAIT1();
        } else {
            CP_WAIT0();
        }
        __syncthreads();

        const unsigned char* bufp = smraw + (kc & 1) * BUFSZ;

        float s[8][4];
#pragma unroll
        for (int n = 0; n < 8; n++) {
            s[n][0] = s[n][1] = s[n][2] = s[n][3] = 0.0f;
            const uint32_t rb = (uint32_t)((n * 8 + g) * KSTR_B);
#pragma unroll
            for (int t = 0; t < 4; t++) {
                const uint32_t co = rb + (uint32_t)((t * 16 + tig * 2) * 2);
                const uint32_t bh0 = *(const uint32_t*)(bufp + SM_KH + co);
                const uint32_t bh1 = *(const uint32_t*)(bufp + SM_KH + co + 16);
                const uint32_t bl0 = *(const uint32_t*)(bufp + SM_KL + co);
                const uint32_t bl1 = *(const uint32_t*)(bufp + SM_KL + co + 16);
                mma16816(s[n], qh[t], bh0, bh1);
                mma16816(s[n], ql[t], bh0, bh1);
                mma16816(s[n], qh[t], bl0, bl1);
            }
        }

        float rm0 = -INFINITY, rm1 = -INFINITY;
#pragma unroll
        for (int n = 0; n < 8; n++) {
            rm0 = fmaxf(rm0, fmaxf(s[n][0], s[n][1]));
            rm1 = fmaxf(rm1, fmaxf(s[n][2], s[n][3]));
        }
        rm0 = fmaxf(rm0, __shfl_xor_sync(0xffffffffu, rm0, 1));
        rm0 = fmaxf(rm0, __shfl_xor_sync(0xffffffffu, rm0, 2));
        rm1 = fmaxf(rm1, __shfl_xor_sync(0xffffffffu, rm1, 1));
        rm1 = fmaxf(rm1, __shfl_xor_sync(0xffffffffu, rm1, 2));

        const float mn0 = fmaxf(m0, rm0), mn1 = fmaxf(m1, rm1);
        const float c0 = fast_exp2(m0 - mn0), c1 = fast_exp2(m1 - mn1);
        m0 = mn0; m1 = mn1;
#pragma unroll
        for (int n = 0; n < 8; n++) {
            o[n][0] *= c0; o[n][1] *= c0;
            o[n][2] *= c1; o[n][3] *= c1;
        }
        float ps0 = 0.0f, ps1 = 0.0f;
#pragma unroll
        for (int n = 0; n < 8; n++) {
            s[n][0] = fast_exp2(s[n][0] - mn0);
            s[n][1] = fast_exp2(s[n][1] - mn0);
            s[n][2] = fast_exp2(s[n][2] - mn1);
            s[n][3] = fast_exp2(s[n][3] - mn1);
            ps0 += s[n][0] + s[n][1];
            ps1 += s[n][2] + s[n][3];
        }
        ps0 += __shfl_xor_sync(0xffffffffu, ps0, 1);
        ps0 += __shfl_xor_sync(0xffffffffu, ps0, 2);
        ps1 += __shfl_xor_sync(0xffffffffu, ps1, 1);
        ps1 += __shfl_xor_sync(0xffffffffu, ps1, 2);
        l0 = l0 * c0 + ps0;
        l1 = l1 * c1 + ps1;

        uint32_t ph[4][4], pl[4][4];
#pragma unroll
        for (int t = 0; t < 4; t++) {
            split_pack(s[2 * t][0],     s[2 * t][1],     ph[t][0], pl[t][0]);
            split_pack(s[2 * t][2],     s[2 * t][3],     ph[t][1], pl[t][1]);
            split_pack(s[2 * t + 1][0], s[2 * t + 1][1], ph[t][2], pl[t][2]);
            split_pack(s[2 * t + 1][2], s[2 * t + 1][3], ph[t][3], pl[t][3]);
        }

#pragma unroll
        for (int n = 0; n < 8; n++) {
            const uint32_t rb = (uint32_t)((n * 8 + g) * KSTR_B);
#pragma unroll
            for (int t = 0; t < 4; t++) {
                const uint32_t co = rb + (uint32_t)((t * 16 + tig * 2) * 2);
                const uint32_t vh0 = *(const uint32_t*)(bufp + SM_VH + co);
                const uint32_t vh1 = *(const uint32_t*)(bufp + SM_VH + co + 16);
                const uint32_t vl0 = *(const uint32_t*)(bufp + SM_VL + co);
                const uint32_t vl1 = *(const uint32_t*)(bufp + SM_VL + co + 16);
                mma16816(o[n], ph[t], vh0, vh1);
                mma16816(o[n], pl[t], vh0, vh1);
                mma16816(o[n], ph[t], vl0, vl1);
            }
        }
        __syncthreads();
    }

    const float inv0 = 1.0f / l0, inv1 = 1.0f / l1;
    const int q0 = qt * 64 + w * 16 + g;
    float* ob = out + (size_t)b * SEQ * HID + (size_t)h * HD;
#pragma unroll
    for (int n = 0; n < 8; n++) {
        float2 w0, w1;
        w0.x = o[n][0] * inv0; w0.y = o[n][1] * inv0;
        w1.x = o[n][2] * inv1; w1.y = o[n][3] * inv1;
        *(float2*)(ob + (size_t)q0 * HID + n * 8 + tig * 2)       = w0;
        *(float2*)(ob + (size_t)(q0 + 8) * HID + n * 8 + tig * 2) = w1;
    }
}

// ---------------------------------------------------------------------------
extern "C" void kernel_launch(void* const* d_in, const int* in_sizes, int n_in,
                              void* d_out, int out_size) {
    const float* x    = (const float*)d_in[0];
    const float* W    = (const float*)d_in[1];
    const float* bias = (const float*)d_in[2];
    float* out = (float*)d_out;

    cudaFuncSetAttribute(qkv_gemm_mma,
                         cudaFuncAttributeMaxDynamicSharedMemorySize, GEMM_SMEM);
    cudaFuncSetAttribute(attn_mma,
                         cudaFuncAttributeMaxDynamicSharedMemorySize, ATTN_SMEM);

    const int splitBlocks = (XELEMS / 4 + WELEMS / 4 + 255) / 256;
    split_inputs<<<splitBlocks, 256>>>(x, W);
    qkv_gemm_mma<<<dim3(NOUT / 128, (NBATCH * SEQ) / 128), 256, GEMM_SMEM>>>(bias);
    attn_mma<<<dim3(SEQ / 64, NBATCH * NHEAD), 128, ATTN_SMEM>>>(out);
}